// round 6
// baseline (speedup 1.0000x reference)
#include <cuda_runtime.h>
#include <cuda_bf16.h>
#include <math.h>
#include <stdint.h>

#define NTOK 32768      // 32*32*32
#define CDIM 128
#define HEADS 8
#define HD 16
#define CF 512

// ---------------- scratch (device globals) -----------------------------------
__device__ float          g_qkv[384 * NTOK];             // fp32 qkv [j][n]
__device__ __nv_bfloat16  g_xh[CDIM * NTOK],  g_xl[CDIM * NTOK];   // x split
__device__ __nv_bfloat16  g_ah[CDIM * NTOK],  g_al[CDIM * NTOK];   // attn split
__device__ float          g_x5[CDIM * NTOK];             // proj out fp32
__device__ float          g_t [CDIM * NTOK];             // inorm1 out fp32 (residual)
__device__ __nv_bfloat16  g_th[CDIM * NTOK],  g_tl[CDIM * NTOK];   // t split
__device__ __nv_bfloat16  g_hh[CF * NTOK],    g_hl[CF * NTOK];     // hidden split
__device__ float          g_y [CDIM * NTOK];             // pre-final-IN
// weight splits
__device__ __nv_bfloat16  g_wqh[384 * CDIM], g_wql[384 * CDIM];
__device__ __nv_bfloat16  g_wph[CDIM * CDIM], g_wpl[CDIM * CDIM];
__device__ __nv_bfloat16  g_w1h[CF * CDIM],  g_w1l[CF * CDIM];
__device__ __nv_bfloat16  g_w2h[CDIM * CF],  g_w2l[CDIM * CF];

// ---------------- helpers -----------------------------------------------------
__device__ __forceinline__ float gelu_f(float x) {
    const float k0 = 0.7978845608028654f;
    const float k1 = 0.044715f;
    return 0.5f * x * (1.0f + tanhf(k0 * (x + k1 * x * x * x)));
}
__device__ __forceinline__ void splitbf(float v, __nv_bfloat16 &h, __nv_bfloat16 &l) {
    h = __float2bfloat16_rn(v);
    l = __float2bfloat16_rn(v - __bfloat162float(h));
}
__device__ __forceinline__ void ldsm4(unsigned &r0, unsigned &r1, unsigned &r2, unsigned &r3, unsigned addr) {
    asm volatile("ldmatrix.sync.aligned.m8n8.x4.shared.b16 {%0,%1,%2,%3}, [%4];"
                 : "=r"(r0), "=r"(r1), "=r"(r2), "=r"(r3) : "r"(addr));
}
__device__ __forceinline__ void ldsm4t(unsigned &r0, unsigned &r1, unsigned &r2, unsigned &r3, unsigned addr) {
    asm volatile("ldmatrix.sync.aligned.m8n8.x4.trans.shared.b16 {%0,%1,%2,%3}, [%4];"
                 : "=r"(r0), "=r"(r1), "=r"(r2), "=r"(r3) : "r"(addr));
}
__device__ __forceinline__ void mma_bf16(float *c, const unsigned *a, const unsigned *b) {
    asm volatile("mma.sync.aligned.m16n8k16.row.col.f32.bf16.bf16.f32 "
                 "{%0,%1,%2,%3},{%4,%5,%6,%7},{%8,%9},{%0,%1,%2,%3};"
                 : "+f"(c[0]), "+f"(c[1]), "+f"(c[2]), "+f"(c[3])
                 : "r"(a[0]), "r"(a[1]), "r"(a[2]), "r"(a[3]), "r"(b[0]), "r"(b[1]));
}
__device__ __forceinline__ void cp16(uint32_t dst, const void* src) {
    asm volatile("cp.async.cg.shared.global [%0], [%1], 16;" :: "r"(dst), "l"(src));
}
__device__ __forceinline__ void cp_commit() { asm volatile("cp.async.commit_group;" ::: "memory"); }
template<int N>
__device__ __forceinline__ void cp_wait() { asm volatile("cp.async.wait_group %0;" :: "n"(N) : "memory"); }

// ---------------- split kernel (fp32 -> bf16 hi/lo) --------------------------
__global__ __launch_bounds__(256)
void split_kernel(const float* __restrict__ in, __nv_bfloat16* __restrict__ h,
                  __nv_bfloat16* __restrict__ l, int n4)
{
    int i = blockIdx.x * 256 + threadIdx.x;
    if (i >= n4) return;
    float4 v = ((const float4*)in)[i];
    __nv_bfloat16 h0,h1,h2,h3,l0,l1,l2,l3;
    splitbf(v.x,h0,l0); splitbf(v.y,h1,l1); splitbf(v.z,h2,l2); splitbf(v.w,h3,l3);
    ushort4 hv = { __bfloat16_as_ushort(h0), __bfloat16_as_ushort(h1),
                   __bfloat16_as_ushort(h2), __bfloat16_as_ushort(h3) };
    ushort4 lv = { __bfloat16_as_ushort(l0), __bfloat16_as_ushort(l1),
                   __bfloat16_as_ushort(l2), __bfloat16_as_ushort(l3) };
    ((ushort4*)h)[i] = hv;
    ((ushort4*)l)[i] = lv;
}

// ---------------- tensor-core GEMM (mma.sync, split-bf16, cp.async pipe) -----
// out[j][n] = sum_k W[j][k]*A[k][n] + b[j].  A [k][n] bf16 hi/lo, W [j][k] bf16 hi/lo.
// Tile: BM=64(j) x BN=128(n) x BK=32.  256 threads = 8 warps (2M x 4N).
// EPI: 0 bias->fp32; 1 gelu->bf16 split; 2 bias+residual->fp32
#define SW 40    // bf16 row stride of W tiles (32 + 8 pad)  -> 80 B
#define SA 136   // bf16 row stride of A tiles (128 + 8 pad) -> 272 B
// stage region byte offsets (relative to stage base)
#define OFF_WH 0
#define OFF_WL 5120
#define OFF_AH 10240
#define OFF_AL 18944
#define ST_BYTES 27648
#define SMEM_TOT (2 * ST_BYTES)

template<int EPI>
__global__ __launch_bounds__(256)
void gemm_tc(const __nv_bfloat16* __restrict__ Ah, const __nv_bfloat16* __restrict__ Al,
             const __nv_bfloat16* __restrict__ Wh, const __nv_bfloat16* __restrict__ Wl,
             const float* __restrict__ bias, const float* __restrict__ Rres,
             float* __restrict__ outf,
             __nv_bfloat16* __restrict__ outh, __nv_bfloat16* __restrict__ outl,
             int Ktot)
{
    extern __shared__ __align__(16) char smem[];
    const uint32_t sb = (uint32_t)__cvta_generic_to_shared(smem);

    const int tid  = threadIdx.x;
    const int lane = tid & 31;
    const int wid  = tid >> 5;
    const int wm   = wid >> 2;          // 0..1 (M warp)
    const int wn   = wid & 3;           // 0..3 (N warp)
    const int gid  = lane >> 2;         // 0..7
    const int tig  = lane & 3;          // 0..3
    const int lm   = lane & 15;
    const int lq   = lane >> 4;

    const int n0 = blockIdx.x * 128;
    const int j0 = blockIdx.y * 64;

    // ldsm fragment byte offsets (relative to region base)
    unsigned aoff[2][2], boff[2][2];
    #pragma unroll
    for (int ma = 0; ma < 2; ma++)
        #pragma unroll
        for (int ka = 0; ka < 2; ka++)
            aoff[ma][ka] = ((wm * 32 + ma * 16 + lm) * SW + ka * 16 + lq * 8) * 2;
    #pragma unroll
    for (int p = 0; p < 2; p++)
        #pragma unroll
        for (int ka = 0; ka < 2; ka++)
            boff[p][ka] = ((ka * 16 + lm) * SA + wn * 32 + p * 16 + lq * 8) * 2;

    // loader indices
    const int wjr = tid >> 2, wse = tid & 3;   // W: row 0..63, seg 0..3 (8 bf16 each)

    float acc[2][4][4];
    #pragma unroll
    for (int a = 0; a < 2; a++)
        #pragma unroll
        for (int b = 0; b < 4; b++)
            #pragma unroll
            for (int c = 0; c < 4; c++) acc[a][b][c] = 0.0f;

    auto prefetch = [&](int ch) {
        const int kc = ch * 32;
        const uint32_t base = sb + (uint32_t)(ch & 1) * ST_BYTES;
        // W tiles: 64 rows x 32 bf16, 4 segs/row
        {
            size_t go = (size_t)(j0 + wjr) * Ktot + kc + wse * 8;
            uint32_t so = (uint32_t)((wjr * SW + wse * 8) * 2);
            cp16(base + OFF_WH + so, &Wh[go]);
            cp16(base + OFF_WL + so, &Wl[go]);
        }
        // A tiles: 32 rows x 128 bf16, 16 segs/row
        #pragma unroll
        for (int i = 0; i < 2; i++) {
            int flat = tid + i * 256;
            int k = flat >> 4, seg = flat & 15;
            size_t go = (size_t)(kc + k) * NTOK + n0 + seg * 8;
            uint32_t so = (uint32_t)((k * SA + seg * 8) * 2);
            cp16(base + OFF_AH + so, &Ah[go]);
            cp16(base + OFF_AL + so, &Al[go]);
        }
        cp_commit();
    };

    const int nch = Ktot / 32;
    prefetch(0);

    for (int ch = 0; ch < nch; ch++) {
        if (ch + 1 < nch) { prefetch(ch + 1); cp_wait<1>(); }
        else             { cp_wait<0>(); }
        __syncthreads();

        const uint32_t base = sb + (uint32_t)(ch & 1) * ST_BYTES;
        #pragma unroll
        for (int ka = 0; ka < 2; ka++) {
            unsigned ah[2][4], al[2][4], bh[4][2], bl[4][2];
            #pragma unroll
            for (int ma = 0; ma < 2; ma++) {
                ldsm4(ah[ma][0], ah[ma][1], ah[ma][2], ah[ma][3], base + OFF_WH + aoff[ma][ka]);
                ldsm4(al[ma][0], al[ma][1], al[ma][2], al[ma][3], base + OFF_WL + aoff[ma][ka]);
            }
            #pragma unroll
            for (int p = 0; p < 2; p++) {
                unsigned r0, r1, r2, r3;
                ldsm4t(r0, r1, r2, r3, base + OFF_AH + boff[p][ka]);
                bh[2 * p][0] = r0; bh[2 * p][1] = r1;
                bh[2 * p + 1][0] = r2; bh[2 * p + 1][1] = r3;
                ldsm4t(r0, r1, r2, r3, base + OFF_AL + boff[p][ka]);
                bl[2 * p][0] = r0; bl[2 * p][1] = r1;
                bl[2 * p + 1][0] = r2; bl[2 * p + 1][1] = r3;
            }
            #pragma unroll
            for (int ma = 0; ma < 2; ma++)
                #pragma unroll
                for (int na = 0; na < 4; na++) {
                    mma_bf16(acc[ma][na], ah[ma], bh[na]);
                    mma_bf16(acc[ma][na], ah[ma], bl[na]);
                    mma_bf16(acc[ma][na], al[ma], bh[na]);
                }
        }
        __syncthreads();
    }

    // epilogue
    #pragma unroll
    for (int ma = 0; ma < 2; ma++) {
        int jA = j0 + wm * 32 + ma * 16 + gid;
        int jB = jA + 8;
        float bA = bias[jA], bB = bias[jB];
        #pragma unroll
        for (int na = 0; na < 4; na++) {
            int n = n0 + wn * 32 + na * 8 + tig * 2;
            float v0 = acc[ma][na][0] + bA;
            float v1 = acc[ma][na][1] + bA;
            float v2 = acc[ma][na][2] + bB;
            float v3 = acc[ma][na][3] + bB;
            if (EPI == 1) {
                v0 = gelu_f(v0); v1 = gelu_f(v1); v2 = gelu_f(v2); v3 = gelu_f(v3);
                __nv_bfloat16 h0,h1,h2,h3,l0,l1,l2,l3;
                splitbf(v0,h0,l0); splitbf(v1,h1,l1);
                splitbf(v2,h2,l2); splitbf(v3,h3,l3);
                ushort2 hA = { __bfloat16_as_ushort(h0), __bfloat16_as_ushort(h1) };
                ushort2 lA = { __bfloat16_as_ushort(l0), __bfloat16_as_ushort(l1) };
                ushort2 hB = { __bfloat16_as_ushort(h2), __bfloat16_as_ushort(h3) };
                ushort2 lB = { __bfloat16_as_ushort(l2), __bfloat16_as_ushort(l3) };
                *(ushort2*)&outh[(size_t)jA * NTOK + n] = hA;
                *(ushort2*)&outl[(size_t)jA * NTOK + n] = lA;
                *(ushort2*)&outh[(size_t)jB * NTOK + n] = hB;
                *(ushort2*)&outl[(size_t)jB * NTOK + n] = lB;
            } else {
                if (EPI == 2) {
                    float2 rA = *(const float2*)&Rres[(size_t)jA * NTOK + n];
                    float2 rB = *(const float2*)&Rres[(size_t)jB * NTOK + n];
                    v0 += rA.x; v1 += rA.y; v2 += rB.x; v3 += rB.y;
                }
                float2 oA = {v0, v1}, oB = {v2, v3};
                *(float2*)&outf[(size_t)jA * NTOK + n] = oA;
                *(float2*)&outf[(size_t)jB * NTOK + n] = oB;
            }
        }
    }
}

// ---------------- neighborhood attention (K=3, 27 taps) ----------------------
__global__ __launch_bounds__(256)
void natten_kernel(const float* __restrict__ qkv,
                   const float* __restrict__ rpb,
                   __nv_bfloat16* __restrict__ outh,
                   __nv_bfloat16* __restrict__ outl)
{
    const int lane = threadIdx.x & 31;
    const int hh   = threadIdx.x >> 5;
    const int ih   = blockIdx.x >> 5;
    const int iw   = blockIdx.x & 31;
    const int iz   = lane;
    const int n    = (ih * 32 + iw) * 32 + iz;

    int sh = ih - 1; sh = sh < 0 ? 0 : (sh > 29 ? 29 : sh);
    int sw = iw - 1; sw = sw < 0 ? 0 : (sw > 29 ? 29 : sw);
    int sz = iz - 1; sz = sz < 0 ? 0 : (sz > 29 ? 29 : sz);

    const float scale = 0.25f;
    float q[HD];
    #pragma unroll
    for (int d = 0; d < HD; d++)
        q[d] = qkv[(size_t)(hh * HD + d) * NTOK + n] * scale;

    float lg[27];
    float mx = -1e30f;
    #pragma unroll
    for (int a = 0; a < 3; a++)
    #pragma unroll
    for (int b = 0; b < 3; b++)
    #pragma unroll
    for (int c = 0; c < 3; c++) {
        int nh = sh + a, nw = sw + b, nz = sz + c;
        int nn = (nh * 32 + nw) * 32 + nz;
        float s = 0.0f;
        #pragma unroll
        for (int d = 0; d < HD; d++)
            s = fmaf(q[d], qkv[(size_t)(CDIM + hh * HD + d) * NTOK + nn], s);
        int rh = nh - ih + 2, rw = nw - iw + 2, rz = nz - iz + 2;
        s += rpb[((hh * 5 + rh) * 5 + rw) * 5 + rz];
        lg[(a * 3 + b) * 3 + c] = s;
        mx = fmaxf(mx, s);
    }

    float denom = 0.0f;
    #pragma unroll
    for (int i = 0; i < 27; i++) { lg[i] = __expf(lg[i] - mx); denom += lg[i]; }
    const float inv = 1.0f / denom;

    float o[HD];
    #pragma unroll
    for (int d = 0; d < HD; d++) o[d] = 0.0f;
    #pragma unroll
    for (int a = 0; a < 3; a++)
    #pragma unroll
    for (int b = 0; b < 3; b++)
    #pragma unroll
    for (int c = 0; c < 3; c++) {
        int nh = sh + a, nw = sw + b, nz = sz + c;
        int nn = (nh * 32 + nw) * 32 + nz;
        float w = lg[(a * 3 + b) * 3 + c] * inv;
        #pragma unroll
        for (int d = 0; d < HD; d++)
            o[d] = fmaf(w, qkv[(size_t)(2 * CDIM + hh * HD + d) * NTOK + nn], o[d]);
    }
    #pragma unroll
    for (int d = 0; d < HD; d++) {
        __nv_bfloat16 vh, vl;
        splitbf(o[d], vh, vl);
        outh[(size_t)(hh * HD + d) * NTOK + n] = vh;
        outl[(size_t)(hh * HD + d) * NTOK + n] = vl;
    }
}

// ---------------- instance norm over N per channel ----------------------------
template<int SPLIT>
__global__ __launch_bounds__(256)
void inorm_kernel(const float* __restrict__ in, float* __restrict__ out,
                  __nv_bfloat16* __restrict__ oh, __nv_bfloat16* __restrict__ ol)
{
    const int c = blockIdx.x;
    const float4* p = (const float4*)(in + (size_t)c * NTOK);
    float s = 0.0f, s2 = 0.0f;
    for (int i = threadIdx.x; i < NTOK / 4; i += 256) {
        float4 v = p[i];
        s  += v.x + v.y + v.z + v.w;
        s2 += v.x * v.x + v.y * v.y + v.z * v.z + v.w * v.w;
    }
    __shared__ float rs[256], rq[256];
    rs[threadIdx.x] = s; rq[threadIdx.x] = s2;
    __syncthreads();
    for (int st = 128; st > 0; st >>= 1) {
        if (threadIdx.x < st) {
            rs[threadIdx.x] += rs[threadIdx.x + st];
            rq[threadIdx.x] += rq[threadIdx.x + st];
        }
        __syncthreads();
    }
    __shared__ float s_mean, s_rstd;
    if (threadIdx.x == 0) {
        float m = rs[0] * (1.0f / NTOK);
        float v = rq[0] * (1.0f / NTOK) - m * m;
        s_mean = m;
        s_rstd = rsqrtf(v + 1e-5f);
    }
    __syncthreads();
    const float m = s_mean, r = s_rstd;
    float4* q = (float4*)(out + (size_t)c * NTOK);
    for (int i = threadIdx.x; i < NTOK / 4; i += 256) {
        float4 v = p[i];
        v.x = (v.x - m) * r; v.y = (v.y - m) * r;
        v.z = (v.z - m) * r; v.w = (v.w - m) * r;
        q[i] = v;
        if (SPLIT) {
            __nv_bfloat16 h0,h1,h2,h3,l0,l1,l2,l3;
            splitbf(v.x,h0,l0); splitbf(v.y,h1,l1); splitbf(v.z,h2,l2); splitbf(v.w,h3,l3);
            ushort4 hv = { __bfloat16_as_ushort(h0), __bfloat16_as_ushort(h1),
                           __bfloat16_as_ushort(h2), __bfloat16_as_ushort(h3) };
            ushort4 lv = { __bfloat16_as_ushort(l0), __bfloat16_as_ushort(l1),
                           __bfloat16_as_ushort(l2), __bfloat16_as_ushort(l3) };
            ((ushort4*)(oh + (size_t)c * NTOK))[i] = hv;
            ((ushort4*)(ol + (size_t)c * NTOK))[i] = lv;
        }
    }
}

// ---------------- launch ------------------------------------------------------
extern "C" void kernel_launch(void* const* d_in, const int* in_sizes, int n_in,
                              void* d_out, int out_size)
{
    (void)in_sizes; (void)n_in; (void)out_size;
    const float* x      = (const float*)d_in[0];
    const float* w_qkv  = (const float*)d_in[1];
    const float* b_qkv  = (const float*)d_in[2];
    const float* rpb    = (const float*)d_in[3];
    const float* w_proj = (const float*)d_in[4];
    const float* b_proj = (const float*)d_in[5];
    const float* w_ffn1 = (const float*)d_in[6];
    const float* b_ffn1 = (const float*)d_in[7];
    const float* w_ffn2 = (const float*)d_in[8];
    const float* b_ffn2 = (const float*)d_in[9];
    float* out = (float*)d_out;

    float *qkv, *x5, *t, *y;
    __nv_bfloat16 *xh,*xl,*ah,*al,*th,*tl,*hh,*hl;
    __nv_bfloat16 *wqh,*wql,*wph,*wpl,*w1h,*w1l,*w2h,*w2l;
    cudaGetSymbolAddress((void**)&qkv, g_qkv);
    cudaGetSymbolAddress((void**)&x5,  g_x5);
    cudaGetSymbolAddress((void**)&t,   g_t);
    cudaGetSymbolAddress((void**)&y,   g_y);
    cudaGetSymbolAddress((void**)&xh,  g_xh);  cudaGetSymbolAddress((void**)&xl, g_xl);
    cudaGetSymbolAddress((void**)&ah,  g_ah);  cudaGetSymbolAddress((void**)&al, g_al);
    cudaGetSymbolAddress((void**)&th,  g_th);  cudaGetSymbolAddress((void**)&tl, g_tl);
    cudaGetSymbolAddress((void**)&hh,  g_hh);  cudaGetSymbolAddress((void**)&hl, g_hl);
    cudaGetSymbolAddress((void**)&wqh, g_wqh); cudaGetSymbolAddress((void**)&wql, g_wql);
    cudaGetSymbolAddress((void**)&wph, g_wph); cudaGetSymbolAddress((void**)&wpl, g_wpl);
    cudaGetSymbolAddress((void**)&w1h, g_w1h); cudaGetSymbolAddress((void**)&w1l, g_w1l);
    cudaGetSymbolAddress((void**)&w2h, g_w2h); cudaGetSymbolAddress((void**)&w2l, g_w2l);

    static int attr_done = 0;
    if (!attr_done) {
        cudaFuncSetAttribute(gemm_tc<0>, cudaFuncAttributeMaxDynamicSharedMemorySize, SMEM_TOT);
        cudaFuncSetAttribute(gemm_tc<1>, cudaFuncAttributeMaxDynamicSharedMemorySize, SMEM_TOT);
        cudaFuncSetAttribute(gemm_tc<2>, cudaFuncAttributeMaxDynamicSharedMemorySize, SMEM_TOT);
        attr_done = 1;
    }

    // 0) splits: x + weights
    split_kernel<<<(CDIM * NTOK / 4 + 255) / 256, 256>>>(x, xh, xl, CDIM * NTOK / 4);
    split_kernel<<<(384 * CDIM / 4 + 255) / 256, 256>>>(w_qkv, wqh, wql, 384 * CDIM / 4);
    split_kernel<<<(CDIM * CDIM / 4 + 255) / 256, 256>>>(w_proj, wph, wpl, CDIM * CDIM / 4);
    split_kernel<<<(CF * CDIM / 4 + 255) / 256, 256>>>(w_ffn1, w1h, w1l, CF * CDIM / 4);
    split_kernel<<<(CDIM * CF / 4 + 255) / 256, 256>>>(w_ffn2, w2h, w2l, CDIM * CF / 4);

    // 1) QKV -> fp32 [384][N]
    gemm_tc<0><<<dim3(NTOK / 128, 384 / 64), 256, SMEM_TOT>>>(
        xh, xl, wqh, wql, b_qkv, nullptr, qkv, nullptr, nullptr, CDIM);
    // 2) natten -> attn split bf16
    natten_kernel<<<1024, 256>>>(qkv, rpb, ah, al);
    // 3) proj -> x5 fp32
    gemm_tc<0><<<dim3(NTOK / 128, 128 / 64), 256, SMEM_TOT>>>(
        ah, al, wph, wpl, b_proj, nullptr, x5, nullptr, nullptr, CDIM);
    // 4) inorm1 -> t fp32 + split
    inorm_kernel<1><<<CDIM, 256>>>(x5, t, th, tl);
    // 5) FFN1 + gelu -> hidden split bf16
    gemm_tc<1><<<dim3(NTOK / 128, 512 / 64), 256, SMEM_TOT>>>(
        th, tl, w1h, w1l, b_ffn1, nullptr, nullptr, hh, hl, CDIM);
    // 6) FFN2 + residual(t) -> y fp32
    gemm_tc<2><<<dim3(NTOK / 128, 128 / 64), 256, SMEM_TOT>>>(
        hh, hl, w2h, w2l, b_ffn2, t, y, nullptr, nullptr, CF);
    // 7) final inorm -> out
    inorm_kernel<0><<<CDIM, 256>>>(y, out, nullptr, nullptr);
}

// round 10
// speedup vs baseline: 1.0165x; 1.0165x over previous
#include <cuda_runtime.h>
#include <cuda_bf16.h>
#include <math.h>
#include <stdint.h>

#define NTOK 32768      // 32*32*32
#define CDIM 128
#define HEADS 8
#define HD 16
#define CF 512

// ---------------- scratch (device globals) -----------------------------------
__device__ float          g_qkv[384 * NTOK];             // fp32 qkv [j][n]
__device__ __nv_bfloat16  g_xh[CDIM * NTOK],  g_xl[CDIM * NTOK];   // x split
__device__ __nv_bfloat16  g_ah[CDIM * NTOK],  g_al[CDIM * NTOK];   // attn split
__device__ float          g_x5[CDIM * NTOK];             // proj out fp32
__device__ float          g_t [CDIM * NTOK];             // inorm1 out fp32 (residual)
__device__ __nv_bfloat16  g_th[CDIM * NTOK],  g_tl[CDIM * NTOK];   // t split
__device__ __nv_bfloat16  g_hh[CF * NTOK],    g_hl[CF * NTOK];     // hidden split
__device__ float          g_y [CDIM * NTOK];             // pre-final-IN
// weight splits
__device__ __nv_bfloat16  g_wqh[384 * CDIM], g_wql[384 * CDIM];
__device__ __nv_bfloat16  g_wph[CDIM * CDIM], g_wpl[CDIM * CDIM];
__device__ __nv_bfloat16  g_w1h[CF * CDIM],  g_w1l[CF * CDIM];
__device__ __nv_bfloat16  g_w2h[CDIM * CF],  g_w2l[CDIM * CF];
// instance-norm stats
__device__ float g_sum[CDIM * 8], g_sq[CDIM * 8];
__device__ float g_mean[CDIM], g_rstd[CDIM];

// ---------------- helpers -----------------------------------------------------
__device__ __forceinline__ float gelu_f(float x) {
    const float k0 = 0.7978845608028654f;
    const float k1 = 0.044715f;
    return 0.5f * x * (1.0f + tanhf(k0 * (x + k1 * x * x * x)));
}
__device__ __forceinline__ void splitbf(float v, __nv_bfloat16 &h, __nv_bfloat16 &l) {
    h = __float2bfloat16_rn(v);
    l = __float2bfloat16_rn(v - __bfloat162float(h));
}
__device__ __forceinline__ void ldsm4(unsigned &r0, unsigned &r1, unsigned &r2, unsigned &r3, unsigned addr) {
    asm volatile("ldmatrix.sync.aligned.m8n8.x4.shared.b16 {%0,%1,%2,%3}, [%4];"
                 : "=r"(r0), "=r"(r1), "=r"(r2), "=r"(r3) : "r"(addr));
}
__device__ __forceinline__ void ldsm4t(unsigned &r0, unsigned &r1, unsigned &r2, unsigned &r3, unsigned addr) {
    asm volatile("ldmatrix.sync.aligned.m8n8.x4.trans.shared.b16 {%0,%1,%2,%3}, [%4];"
                 : "=r"(r0), "=r"(r1), "=r"(r2), "=r"(r3) : "r"(addr));
}
__device__ __forceinline__ void mma_bf16(float *c, const unsigned *a, const unsigned *b) {
    asm volatile("mma.sync.aligned.m16n8k16.row.col.f32.bf16.bf16.f32 "
                 "{%0,%1,%2,%3},{%4,%5,%6,%7},{%8,%9},{%0,%1,%2,%3};"
                 : "+f"(c[0]), "+f"(c[1]), "+f"(c[2]), "+f"(c[3])
                 : "r"(a[0]), "r"(a[1]), "r"(a[2]), "r"(a[3]), "r"(b[0]), "r"(b[1]));
}
__device__ __forceinline__ void cp16(uint32_t dst, const void* src) {
    asm volatile("cp.async.cg.shared.global [%0], [%1], 16;" :: "r"(dst), "l"(src));
}
__device__ __forceinline__ void cp_commit() { asm volatile("cp.async.commit_group;" ::: "memory"); }
template<int N>
__device__ __forceinline__ void cp_wait() { asm volatile("cp.async.wait_group %0;" :: "n"(N) : "memory"); }

// ---------------- split kernels (fp32 -> bf16 hi/lo) --------------------------
__device__ __forceinline__ void split4(const float* __restrict__ in,
                                       __nv_bfloat16* __restrict__ h,
                                       __nv_bfloat16* __restrict__ l, int i)
{
    float4 v = ((const float4*)in)[i];
    __nv_bfloat16 h0,h1,h2,h3,l0,l1,l2,l3;
    splitbf(v.x,h0,l0); splitbf(v.y,h1,l1); splitbf(v.z,h2,l2); splitbf(v.w,h3,l3);
    ushort4 hv = { __bfloat16_as_ushort(h0), __bfloat16_as_ushort(h1),
                   __bfloat16_as_ushort(h2), __bfloat16_as_ushort(h3) };
    ushort4 lv = { __bfloat16_as_ushort(l0), __bfloat16_as_ushort(l1),
                   __bfloat16_as_ushort(l2), __bfloat16_as_ushort(l3) };
    ((ushort4*)h)[i] = hv;
    ((ushort4*)l)[i] = lv;
}

__global__ __launch_bounds__(256)
void split_kernel(const float* __restrict__ in, __nv_bfloat16* __restrict__ h,
                  __nv_bfloat16* __restrict__ l, int n4)
{
    int i = blockIdx.x * 256 + threadIdx.x;
    if (i < n4) split4(in, h, l, i);
}

// all 4 weight splits in one launch. blocks: [0,48) wq, [48,64) wp, [64,128) w1, [128,192) w2
__global__ __launch_bounds__(256)
void wsplit_kernel(const float* wq, __nv_bfloat16* wqh, __nv_bfloat16* wql,
                   const float* wp, __nv_bfloat16* wph, __nv_bfloat16* wpl,
                   const float* w1, __nv_bfloat16* w1h, __nv_bfloat16* w1l,
                   const float* w2, __nv_bfloat16* w2h, __nv_bfloat16* w2l)
{
    int b = blockIdx.x;
    if (b < 48)        split4(wq, wqh, wql, b * 256 + threadIdx.x);
    else if (b < 64)   split4(wp, wph, wpl, (b - 48) * 256 + threadIdx.x);
    else if (b < 128)  split4(w1, w1h, w1l, (b - 64) * 256 + threadIdx.x);
    else               split4(w2, w2h, w2l, (b - 128) * 256 + threadIdx.x);
}

// ---------------- tensor-core GEMM (mma.sync, split-bf16, cp.async pipe) -----
#define SW 40    // bf16 row stride of W tiles (32 + 8 pad)
#define SA 136   // bf16 row stride of A tiles (128 + 8 pad)
#define OFF_WH 0
#define OFF_WL 5120
#define OFF_AH 10240
#define OFF_AL 18944
#define ST_BYTES 27648
#define SMEM_TOT (2 * ST_BYTES)

template<int EPI>
__global__ __launch_bounds__(256)
void gemm_tc(const __nv_bfloat16* __restrict__ Ah, const __nv_bfloat16* __restrict__ Al,
             const __nv_bfloat16* __restrict__ Wh, const __nv_bfloat16* __restrict__ Wl,
             const float* __restrict__ bias, const float* __restrict__ Rres,
             float* __restrict__ outf,
             __nv_bfloat16* __restrict__ outh, __nv_bfloat16* __restrict__ outl,
             int Ktot)
{
    extern __shared__ __align__(16) char smem[];
    const uint32_t sb = (uint32_t)__cvta_generic_to_shared(smem);

    const int tid  = threadIdx.x;
    const int lane = tid & 31;
    const int wid  = tid >> 5;
    const int wm   = wid >> 2;
    const int wn   = wid & 3;
    const int gid  = lane >> 2;
    const int tig  = lane & 3;
    const int lm   = lane & 15;
    const int lq   = lane >> 4;

    const int n0 = blockIdx.x * 128;
    const int j0 = blockIdx.y * 64;

    unsigned aoff[2][2], boff[2][2];
    #pragma unroll
    for (int ma = 0; ma < 2; ma++)
        #pragma unroll
        for (int ka = 0; ka < 2; ka++)
            aoff[ma][ka] = ((wm * 32 + ma * 16 + lm) * SW + ka * 16 + lq * 8) * 2;
    #pragma unroll
    for (int p = 0; p < 2; p++)
        #pragma unroll
        for (int ka = 0; ka < 2; ka++)
            boff[p][ka] = ((ka * 16 + lm) * SA + wn * 32 + p * 16 + lq * 8) * 2;

    const int wjr = tid >> 2, wse = tid & 3;

    float acc[2][4][4];
    #pragma unroll
    for (int a = 0; a < 2; a++)
        #pragma unroll
        for (int b = 0; b < 4; b++)
            #pragma unroll
            for (int c = 0; c < 4; c++) acc[a][b][c] = 0.0f;

    auto prefetch = [&](int ch) {
        const int kc = ch * 32;
        const uint32_t base = sb + (uint32_t)(ch & 1) * ST_BYTES;
        {
            size_t go = (size_t)(j0 + wjr) * Ktot + kc + wse * 8;
            uint32_t so = (uint32_t)((wjr * SW + wse * 8) * 2);
            cp16(base + OFF_WH + so, &Wh[go]);
            cp16(base + OFF_WL + so, &Wl[go]);
        }
        #pragma unroll
        for (int i = 0; i < 2; i++) {
            int flat = tid + i * 256;
            int k = flat >> 4, seg = flat & 15;
            size_t go = (size_t)(kc + k) * NTOK + n0 + seg * 8;
            uint32_t so = (uint32_t)((k * SA + seg * 8) * 2);
            cp16(base + OFF_AH + so, &Ah[go]);
            cp16(base + OFF_AL + so, &Al[go]);
        }
        cp_commit();
    };

    const int nch = Ktot / 32;
    prefetch(0);

    for (int ch = 0; ch < nch; ch++) {
        if (ch + 1 < nch) { prefetch(ch + 1); cp_wait<1>(); }
        else             { cp_wait<0>(); }
        __syncthreads();

        const uint32_t base = sb + (uint32_t)(ch & 1) * ST_BYTES;
        #pragma unroll
        for (int ka = 0; ka < 2; ka++) {
            unsigned ah[2][4], al[2][4], bh[4][2], bl[4][2];
            #pragma unroll
            for (int ma = 0; ma < 2; ma++) {
                ldsm4(ah[ma][0], ah[ma][1], ah[ma][2], ah[ma][3], base + OFF_WH + aoff[ma][ka]);
                ldsm4(al[ma][0], al[ma][1], al[ma][2], al[ma][3], base + OFF_WL + aoff[ma][ka]);
            }
            #pragma unroll
            for (int p = 0; p < 2; p++) {
                unsigned r0, r1, r2, r3;
                ldsm4t(r0, r1, r2, r3, base + OFF_AH + boff[p][ka]);
                bh[2 * p][0] = r0; bh[2 * p][1] = r1;
                bh[2 * p + 1][0] = r2; bh[2 * p + 1][1] = r3;
                ldsm4t(r0, r1, r2, r3, base + OFF_AL + boff[p][ka]);
                bl[2 * p][0] = r0; bl[2 * p][1] = r1;
                bl[2 * p + 1][0] = r2; bl[2 * p + 1][1] = r3;
            }
            #pragma unroll
            for (int ma = 0; ma < 2; ma++)
                #pragma unroll
                for (int na = 0; na < 4; na++) {
                    mma_bf16(acc[ma][na], ah[ma], bh[na]);
                    mma_bf16(acc[ma][na], ah[ma], bl[na]);
                    mma_bf16(acc[ma][na], al[ma], bh[na]);
                }
        }
        __syncthreads();
    }

    #pragma unroll
    for (int ma = 0; ma < 2; ma++) {
        int jA = j0 + wm * 32 + ma * 16 + gid;
        int jB = jA + 8;
        float bA = bias[jA], bB = bias[jB];
        #pragma unroll
        for (int na = 0; na < 4; na++) {
            int n = n0 + wn * 32 + na * 8 + tig * 2;
            float v0 = acc[ma][na][0] + bA;
            float v1 = acc[ma][na][1] + bA;
            float v2 = acc[ma][na][2] + bB;
            float v3 = acc[ma][na][3] + bB;
            if (EPI == 1) {
                v0 = gelu_f(v0); v1 = gelu_f(v1); v2 = gelu_f(v2); v3 = gelu_f(v3);
                __nv_bfloat16 h0,h1,h2,h3,l0,l1,l2,l3;
                splitbf(v0,h0,l0); splitbf(v1,h1,l1);
                splitbf(v2,h2,l2); splitbf(v3,h3,l3);
                ushort2 hA = { __bfloat16_as_ushort(h0), __bfloat16_as_ushort(h1) };
                ushort2 lA = { __bfloat16_as_ushort(l0), __bfloat16_as_ushort(l1) };
                ushort2 hB = { __bfloat16_as_ushort(h2), __bfloat16_as_ushort(h3) };
                ushort2 lB = { __bfloat16_as_ushort(l2), __bfloat16_as_ushort(l3) };
                *(ushort2*)&outh[(size_t)jA * NTOK + n] = hA;
                *(ushort2*)&outl[(size_t)jA * NTOK + n] = lA;
                *(ushort2*)&outh[(size_t)jB * NTOK + n] = hB;
                *(ushort2*)&outl[(size_t)jB * NTOK + n] = lB;
            } else {
                if (EPI == 2) {
                    float2 rA = *(const float2*)&Rres[(size_t)jA * NTOK + n];
                    float2 rB = *(const float2*)&Rres[(size_t)jB * NTOK + n];
                    v0 += rA.x; v1 += rA.y; v2 += rB.x; v3 += rB.y;
                }
                float2 oA = {v0, v1}, oB = {v2, v3};
                *(float2*)&outf[(size_t)jA * NTOK + n] = oA;
                *(float2*)&outf[(size_t)jB * NTOK + n] = oB;
            }
        }
    }
}

// ---------------- neighborhood attention (K=3, 27 taps), z via warp shuffle ---
__global__ __launch_bounds__(256)
void natten_kernel(const float* __restrict__ qkv,
                   const float* __restrict__ rpb,
                   __nv_bfloat16* __restrict__ outh,
                   __nv_bfloat16* __restrict__ outl)
{
    const int lane = threadIdx.x & 31;
    const int hh   = threadIdx.x >> 5;
    const int ih   = blockIdx.x >> 5;
    const int iw   = blockIdx.x & 31;
    const int iz   = lane;
    const int n    = (ih * 32 + iw) * 32 + iz;

    int sh = ih - 1; sh = sh < 0 ? 0 : (sh > 29 ? 29 : sh);
    int sw = iw - 1; sw = sw < 0 ? 0 : (sw > 29 ? 29 : sw);
    int sz = iz - 1; sz = sz < 0 ? 0 : (sz > 29 ? 29 : sz);

    const float scale = 0.25f;
    float q[HD];
    #pragma unroll
    for (int d = 0; d < HD; d++)
        q[d] = qkv[(size_t)(hh * HD + d) * NTOK + n] * scale;

    // pass 1: logits. each lane loads k for its OWN z; z-taps via shuffle.
    float lg[27];
    float mx = -1e30f;
    #pragma unroll
    for (int a = 0; a < 3; a++)
    #pragma unroll
    for (int b = 0; b < 3; b++) {
        const int nh = sh + a, nw = sw + b;
        const size_t base = (size_t)(CDIM + hh * HD) * NTOK + (nh * 32 + nw) * 32 + lane;
        float kown[HD];
        #pragma unroll
        for (int d = 0; d < HD; d++)
            kown[d] = qkv[base + (size_t)d * NTOK];
        const int rh = nh - ih + 2, rw = nw - iw + 2;
        #pragma unroll
        for (int c = 0; c < 3; c++) {
            const int srcl = sz + c;
            float s = 0.0f;
            #pragma unroll
            for (int d = 0; d < HD; d++)
                s = fmaf(q[d], __shfl_sync(0xffffffffu, kown[d], srcl), s);
            const int rz = srcl - iz + 2;
            s += rpb[((hh * 5 + rh) * 5 + rw) * 5 + rz];
            lg[(a * 3 + b) * 3 + c] = s;
            mx = fmaxf(mx, s);
        }
    }

    float denom = 0.0f;
    #pragma unroll
    for (int i = 0; i < 27; i++) { lg[i] = __expf(lg[i] - mx); denom += lg[i]; }
    const float inv = 1.0f / denom;

    // pass 2: output accumulation, v via shuffle.
    float o[HD];
    #pragma unroll
    for (int d = 0; d < HD; d++) o[d] = 0.0f;
    #pragma unroll
    for (int a = 0; a < 3; a++)
    #pragma unroll
    for (int b = 0; b < 3; b++) {
        const int nh = sh + a, nw = sw + b;
        const size_t base = (size_t)(2 * CDIM + hh * HD) * NTOK + (nh * 32 + nw) * 32 + lane;
        float vown[HD];
        #pragma unroll
        for (int d = 0; d < HD; d++)
            vown[d] = qkv[base + (size_t)d * NTOK];
        #pragma unroll
        for (int c = 0; c < 3; c++) {
            const int srcl = sz + c;
            const float w = lg[(a * 3 + b) * 3 + c] * inv;
            #pragma unroll
            for (int d = 0; d < HD; d++)
                o[d] = fmaf(w, __shfl_sync(0xffffffffu, vown[d], srcl), o[d]);
        }
    }
    #pragma unroll
    for (int d = 0; d < HD; d++) {
        __nv_bfloat16 vh, vl;
        splitbf(o[d], vh, vl);
        outh[(size_t)(hh * HD + d) * NTOK + n] = vh;
        outl[(size_t)(hh * HD + d) * NTOK + n] = vl;
    }
}

// ---------------- instance norm: 3-phase, 1024-way parallel -------------------
__global__ __launch_bounds__(256)
void in_part_kernel(const float* __restrict__ in)
{
    const int c = blockIdx.x >> 3, seg = blockIdx.x & 7;
    const float4* p = (const float4*)(in + (size_t)c * NTOK + seg * 4096);
    float s = 0.0f, s2 = 0.0f;
    #pragma unroll
    for (int i = 0; i < 4; i++) {
        float4 v = p[threadIdx.x + i * 256];
        s  += v.x + v.y + v.z + v.w;
        s2 += v.x * v.x + v.y * v.y + v.z * v.z + v.w * v.w;
    }
    // warp + block reduce
    #pragma unroll
    for (int o = 16; o > 0; o >>= 1) {
        s  += __shfl_down_sync(0xffffffffu, s,  o);
        s2 += __shfl_down_sync(0xffffffffu, s2, o);
    }
    __shared__ float rs[8], rq[8];
    if ((threadIdx.x & 31) == 0) { rs[threadIdx.x >> 5] = s; rq[threadIdx.x >> 5] = s2; }
    __syncthreads();
    if (threadIdx.x == 0) {
        float ts = 0.0f, tq = 0.0f;
        #pragma unroll
        for (int i = 0; i < 8; i++) { ts += rs[i]; tq += rq[i]; }
        g_sum[c * 8 + seg] = ts;
        g_sq [c * 8 + seg] = tq;
    }
}

__global__ __launch_bounds__(128)
void in_fin_kernel()
{
    const int c = threadIdx.x;
    float s = 0.0f, s2 = 0.0f;
    #pragma unroll
    for (int i = 0; i < 8; i++) { s += g_sum[c * 8 + i]; s2 += g_sq[c * 8 + i]; }
    float m = s * (1.0f / NTOK);
    float v = s2 * (1.0f / NTOK) - m * m;
    g_mean[c] = m;
    g_rstd[c] = rsqrtf(v + 1e-5f);
}

template<int SPLIT>
__global__ __launch_bounds__(256)
void in_norm_kernel(const float* __restrict__ in, float* __restrict__ out,
                    __nv_bfloat16* __restrict__ oh, __nv_bfloat16* __restrict__ ol)
{
    const int c = blockIdx.x >> 3, seg = blockIdx.x & 7;
    const float m = g_mean[c], r = g_rstd[c];
    const size_t off = (size_t)c * NTOK + seg * 4096;
    const float4* p = (const float4*)(in + off);
    float4* qo = (float4*)(out + off);
    #pragma unroll
    for (int i = 0; i < 4; i++) {
        int idx = threadIdx.x + i * 256;
        float4 v = p[idx];
        v.x = (v.x - m) * r; v.y = (v.y - m) * r;
        v.z = (v.z - m) * r; v.w = (v.w - m) * r;
        qo[idx] = v;
        if (SPLIT) {
            __nv_bfloat16 h0,h1,h2,h3,l0,l1,l2,l3;
            splitbf(v.x,h0,l0); splitbf(v.y,h1,l1); splitbf(v.z,h2,l2); splitbf(v.w,h3,l3);
            ushort4 hv = { __bfloat16_as_ushort(h0), __bfloat16_as_ushort(h1),
                           __bfloat16_as_ushort(h2), __bfloat16_as_ushort(h3) };
            ushort4 lv = { __bfloat16_as_ushort(l0), __bfloat16_as_ushort(l1),
                           __bfloat16_as_ushort(l2), __bfloat16_as_ushort(l3) };
            ((ushort4*)(oh + off))[idx] = hv;
            ((ushort4*)(ol + off))[idx] = lv;
        }
    }
}

// ---------------- launch ------------------------------------------------------
extern "C" void kernel_launch(void* const* d_in, const int* in_sizes, int n_in,
                              void* d_out, int out_size)
{
    (void)in_sizes; (void)n_in; (void)out_size;
    const float* x      = (const float*)d_in[0];
    const float* w_qkv  = (const float*)d_in[1];
    const float* b_qkv  = (const float*)d_in[2];
    const float* rpb    = (const float*)d_in[3];
    const float* w_proj = (const float*)d_in[4];
    const float* b_proj = (const float*)d_in[5];
    const float* w_ffn1 = (const float*)d_in[6];
    const float* b_ffn1 = (const float*)d_in[7];
    const float* w_ffn2 = (const float*)d_in[8];
    const float* b_ffn2 = (const float*)d_in[9];
    float* out = (float*)d_out;

    float *qkv, *x5, *t, *y;
    __nv_bfloat16 *xh,*xl,*ah,*al,*th,*tl,*hh,*hl;
    __nv_bfloat16 *wqh,*wql,*wph,*wpl,*w1h,*w1l,*w2h,*w2l;
    cudaGetSymbolAddress((void**)&qkv, g_qkv);
    cudaGetSymbolAddress((void**)&x5,  g_x5);
    cudaGetSymbolAddress((void**)&t,   g_t);
    cudaGetSymbolAddress((void**)&y,   g_y);
    cudaGetSymbolAddress((void**)&xh,  g_xh);  cudaGetSymbolAddress((void**)&xl, g_xl);
    cudaGetSymbolAddress((void**)&ah,  g_ah);  cudaGetSymbolAddress((void**)&al, g_al);
    cudaGetSymbolAddress((void**)&th,  g_th);  cudaGetSymbolAddress((void**)&tl, g_tl);
    cudaGetSymbolAddress((void**)&hh,  g_hh);  cudaGetSymbolAddress((void**)&hl, g_hl);
    cudaGetSymbolAddress((void**)&wqh, g_wqh); cudaGetSymbolAddress((void**)&wql, g_wql);
    cudaGetSymbolAddress((void**)&wph, g_wph); cudaGetSymbolAddress((void**)&wpl, g_wpl);
    cudaGetSymbolAddress((void**)&w1h, g_w1h); cudaGetSymbolAddress((void**)&w1l, g_w1l);
    cudaGetSymbolAddress((void**)&w2h, g_w2h); cudaGetSymbolAddress((void**)&w2l, g_w2l);

    cudaFuncSetAttribute(gemm_tc<0>, cudaFuncAttributeMaxDynamicSharedMemorySize, SMEM_TOT);
    cudaFuncSetAttribute(gemm_tc<1>, cudaFuncAttributeMaxDynamicSharedMemorySize, SMEM_TOT);
    cudaFuncSetAttribute(gemm_tc<2>, cudaFuncAttributeMaxDynamicSharedMemorySize, SMEM_TOT);

    // 0) splits: x (4096 blocks) + all weights (192 blocks, one launch)
    split_kernel<<<4096, 256>>>(x, xh, xl, CDIM * NTOK / 4);
    wsplit_kernel<<<192, 256>>>(w_qkv, wqh, wql, w_proj, wph, wpl,
                                w_ffn1, w1h, w1l, w_ffn2, w2h, w2l);

    // 1) QKV -> fp32 [384][N]
    gemm_tc<0><<<dim3(NTOK / 128, 384 / 64), 256, SMEM_TOT>>>(
        xh, xl, wqh, wql, b_qkv, nullptr, qkv, nullptr, nullptr, CDIM);
    // 2) natten -> attn split bf16
    natten_kernel<<<1024, 256>>>(qkv, rpb, ah, al);
    // 3) proj -> x5 fp32
    gemm_tc<0><<<dim3(NTOK / 128, 128 / 64), 256, SMEM_TOT>>>(
        ah, al, wph, wpl, b_proj, nullptr, x5, nullptr, nullptr, CDIM);
    // 4) inorm1 -> t fp32 + split
    in_part_kernel<<<1024, 256>>>(x5);
    in_fin_kernel<<<1, 128>>>();
    in_norm_kernel<1><<<1024, 256>>>(x5, t, th, tl);
    // 5) FFN1 + gelu -> hidden split bf16
    gemm_tc<1><<<dim3(NTOK / 128, 512 / 64), 256, SMEM_TOT>>>(
        th, tl, w1h, w1l, b_ffn1, nullptr, nullptr, hh, hl, CDIM);
    // 6) FFN2 + residual(t) -> y fp32
    gemm_tc<2><<<dim3(NTOK / 128, 128 / 64), 256, SMEM_TOT>>>(
        hh, hl, w2h, w2l, b_ffn2, t, y, nullptr, nullptr, CF);
    // 7) final inorm -> out
    in_part_kernel<<<1024, 256>>>(y);
    in_fin_kernel<<<1, 128>>>();
    in_norm_kernel<0><<<1024, 256>>>(y, out, nullptr, nullptr);
}

// round 13
// speedup vs baseline: 1.0173x; 1.0008x over previous
#include <cuda_runtime.h>
#include <cuda_bf16.h>
#include <math.h>
#include <stdint.h>

#define NTOK 32768      // 32*32*32
#define CDIM 128
#define HEADS 8
#define HD 16
#define CF 512

// ---------------- scratch (device globals) -----------------------------------
__device__ float          g_qkv[384 * NTOK];             // fp32 qkv [j][n]
__device__ __nv_bfloat16  g_xh[CDIM * NTOK],  g_xl[CDIM * NTOK];   // x split
__device__ __nv_bfloat16  g_ah[CDIM * NTOK],  g_al[CDIM * NTOK];   // attn split
__device__ float          g_x5[CDIM * NTOK];             // proj out fp32
__device__ float          g_t [CDIM * NTOK];             // inorm1 out fp32 (residual)
__device__ __nv_bfloat16  g_th[CDIM * NTOK],  g_tl[CDIM * NTOK];   // t split
__device__ __nv_bfloat16  g_hh[CF * NTOK],    g_hl[CF * NTOK];     // hidden split
__device__ float          g_y [CDIM * NTOK];             // pre-final-IN
// weight splits
__device__ __nv_bfloat16  g_wqh[384 * CDIM], g_wql[384 * CDIM];
__device__ __nv_bfloat16  g_wph[CDIM * CDIM], g_wpl[CDIM * CDIM];
__device__ __nv_bfloat16  g_w1h[CF * CDIM],  g_w1l[CF * CDIM];
__device__ __nv_bfloat16  g_w2h[CDIM * CF],  g_w2l[CDIM * CF];
// instance-norm stats
__device__ float g_sum[CDIM * 8], g_sq[CDIM * 8];
__device__ float g_mean[CDIM], g_rstd[CDIM];

// ---------------- helpers -----------------------------------------------------
__device__ __forceinline__ float gelu_f(float x) {
    const float k0 = 0.7978845608028654f;
    const float k1 = 0.044715f;
    return 0.5f * x * (1.0f + tanhf(k0 * (x + k1 * x * x * x)));
}
__device__ __forceinline__ void splitbf(float v, __nv_bfloat16 &h, __nv_bfloat16 &l) {
    h = __float2bfloat16_rn(v);
    l = __float2bfloat16_rn(v - __bfloat162float(h));
}
__device__ __forceinline__ void ldsm4(unsigned &r0, unsigned &r1, unsigned &r2, unsigned &r3, unsigned addr) {
    asm volatile("ldmatrix.sync.aligned.m8n8.x4.shared.b16 {%0,%1,%2,%3}, [%4];"
                 : "=r"(r0), "=r"(r1), "=r"(r2), "=r"(r3) : "r"(addr));
}
__device__ __forceinline__ void ldsm4t(unsigned &r0, unsigned &r1, unsigned &r2, unsigned &r3, unsigned addr) {
    asm volatile("ldmatrix.sync.aligned.m8n8.x4.trans.shared.b16 {%0,%1,%2,%3}, [%4];"
                 : "=r"(r0), "=r"(r1), "=r"(r2), "=r"(r3) : "r"(addr));
}
__device__ __forceinline__ void mma_bf16(float *c, const unsigned *a, const unsigned *b) {
    asm volatile("mma.sync.aligned.m16n8k16.row.col.f32.bf16.bf16.f32 "
                 "{%0,%1,%2,%3},{%4,%5,%6,%7},{%8,%9},{%0,%1,%2,%3};"
                 : "+f"(c[0]), "+f"(c[1]), "+f"(c[2]), "+f"(c[3])
                 : "r"(a[0]), "r"(a[1]), "r"(a[2]), "r"(a[3]), "r"(b[0]), "r"(b[1]));
}
__device__ __forceinline__ void cp16(uint32_t dst, const void* src) {
    asm volatile("cp.async.cg.shared.global [%0], [%1], 16;" :: "r"(dst), "l"(src));
}
__device__ __forceinline__ void cp_commit() { asm volatile("cp.async.commit_group;" ::: "memory"); }
template<int N>
__device__ __forceinline__ void cp_wait() { asm volatile("cp.async.wait_group %0;" :: "n"(N) : "memory"); }

// ---------------- split kernels (fp32 -> bf16 hi/lo) --------------------------
__device__ __forceinline__ void split4(const float* __restrict__ in,
                                       __nv_bfloat16* __restrict__ h,
                                       __nv_bfloat16* __restrict__ l, int i)
{
    float4 v = ((const float4*)in)[i];
    __nv_bfloat16 h0,h1,h2,h3,l0,l1,l2,l3;
    splitbf(v.x,h0,l0); splitbf(v.y,h1,l1); splitbf(v.z,h2,l2); splitbf(v.w,h3,l3);
    ushort4 hv = { __bfloat16_as_ushort(h0), __bfloat16_as_ushort(h1),
                   __bfloat16_as_ushort(h2), __bfloat16_as_ushort(h3) };
    ushort4 lv = { __bfloat16_as_ushort(l0), __bfloat16_as_ushort(l1),
                   __bfloat16_as_ushort(l2), __bfloat16_as_ushort(l3) };
    ((ushort4*)h)[i] = hv;
    ((ushort4*)l)[i] = lv;
}

__global__ __launch_bounds__(256)
void split_kernel(const float* __restrict__ in, __nv_bfloat16* __restrict__ h,
                  __nv_bfloat16* __restrict__ l, int n4)
{
    int i = blockIdx.x * 256 + threadIdx.x;
    if (i < n4) split4(in, h, l, i);
}

// all 4 weight splits in one launch. blocks: [0,48) wq, [48,64) wp, [64,128) w1, [128,192) w2
__global__ __launch_bounds__(256)
void wsplit_kernel(const float* wq, __nv_bfloat16* wqh, __nv_bfloat16* wql,
                   const float* wp, __nv_bfloat16* wph, __nv_bfloat16* wpl,
                   const float* w1, __nv_bfloat16* w1h, __nv_bfloat16* w1l,
                   const float* w2, __nv_bfloat16* w2h, __nv_bfloat16* w2l)
{
    int b = blockIdx.x;
    if (b < 48)        split4(wq, wqh, wql, b * 256 + threadIdx.x);
    else if (b < 64)   split4(wp, wph, wpl, (b - 48) * 256 + threadIdx.x);
    else if (b < 128)  split4(w1, w1h, w1l, (b - 64) * 256 + threadIdx.x);
    else               split4(w2, w2h, w2l, (b - 128) * 256 + threadIdx.x);
}

// ---------------- tensor-core GEMM (mma.sync, split-bf16, cp.async pipe) -----
#define SW 40    // bf16 row stride of W tiles (32 + 8 pad)
#define SA 136   // bf16 row stride of A tiles (128 + 8 pad)
#define OFF_WH 0
#define OFF_WL 5120
#define OFF_AH 10240
#define OFF_AL 18944
#define ST_BYTES 27648
#define SMEM_TOT (2 * ST_BYTES)

template<int EPI>
__global__ __launch_bounds__(256)
void gemm_tc(const __nv_bfloat16* __restrict__ Ah, const __nv_bfloat16* __restrict__ Al,
             const __nv_bfloat16* __restrict__ Wh, const __nv_bfloat16* __restrict__ Wl,
             const float* __restrict__ bias, const float* __restrict__ Rres,
             float* __restrict__ outf,
             __nv_bfloat16* __restrict__ outh, __nv_bfloat16* __restrict__ outl,
             int Ktot)
{
    extern __shared__ __align__(16) char smem[];
    const uint32_t sb = (uint32_t)__cvta_generic_to_shared(smem);

    const int tid  = threadIdx.x;
    const int lane = tid & 31;
    const int wid  = tid >> 5;
    const int wm   = wid >> 2;
    const int wn   = wid & 3;
    const int gid  = lane >> 2;
    const int tig  = lane & 3;
    const int lm   = lane & 15;
    const int lq   = lane >> 4;

    const int n0 = blockIdx.x * 128;
    const int j0 = blockIdx.y * 64;

    unsigned aoff[2][2], boff[2][2];
    #pragma unroll
    for (int ma = 0; ma < 2; ma++)
        #pragma unroll
        for (int ka = 0; ka < 2; ka++)
            aoff[ma][ka] = ((wm * 32 + ma * 16 + lm) * SW + ka * 16 + lq * 8) * 2;
    #pragma unroll
    for (int p = 0; p < 2; p++)
        #pragma unroll
        for (int ka = 0; ka < 2; ka++)
            boff[p][ka] = ((ka * 16 + lm) * SA + wn * 32 + p * 16 + lq * 8) * 2;

    const int wjr = tid >> 2, wse = tid & 3;

    float acc[2][4][4];
    #pragma unroll
    for (int a = 0; a < 2; a++)
        #pragma unroll
        for (int b = 0; b < 4; b++)
            #pragma unroll
            for (int c = 0; c < 4; c++) acc[a][b][c] = 0.0f;

    auto prefetch = [&](int ch) {
        const int kc = ch * 32;
        const uint32_t base = sb + (uint32_t)(ch & 1) * ST_BYTES;
        {
            size_t go = (size_t)(j0 + wjr) * Ktot + kc + wse * 8;
            uint32_t so = (uint32_t)((wjr * SW + wse * 8) * 2);
            cp16(base + OFF_WH + so, &Wh[go]);
            cp16(base + OFF_WL + so, &Wl[go]);
        }
        #pragma unroll
        for (int i = 0; i < 2; i++) {
            int flat = tid + i * 256;
            int k = flat >> 4, seg = flat & 15;
            size_t go = (size_t)(kc + k) * NTOK + n0 + seg * 8;
            uint32_t so = (uint32_t)((k * SA + seg * 8) * 2);
            cp16(base + OFF_AH + so, &Ah[go]);
            cp16(base + OFF_AL + so, &Al[go]);
        }
        cp_commit();
    };

    const int nch = Ktot / 32;
    prefetch(0);

    for (int ch = 0; ch < nch; ch++) {
        if (ch + 1 < nch) { prefetch(ch + 1); cp_wait<1>(); }
        else             { cp_wait<0>(); }
        __syncthreads();

        const uint32_t base = sb + (uint32_t)(ch & 1) * ST_BYTES;
        #pragma unroll
        for (int ka = 0; ka < 2; ka++) {
            unsigned ah[2][4], al[2][4], bh[4][2], bl[4][2];
            #pragma unroll
            for (int ma = 0; ma < 2; ma++) {
                ldsm4(ah[ma][0], ah[ma][1], ah[ma][2], ah[ma][3], base + OFF_WH + aoff[ma][ka]);
                ldsm4(al[ma][0], al[ma][1], al[ma][2], al[ma][3], base + OFF_WL + aoff[ma][ka]);
            }
            #pragma unroll
            for (int p = 0; p < 2; p++) {
                unsigned r0, r1, r2, r3;
                ldsm4t(r0, r1, r2, r3, base + OFF_AH + boff[p][ka]);
                bh[2 * p][0] = r0; bh[2 * p][1] = r1;
                bh[2 * p + 1][0] = r2; bh[2 * p + 1][1] = r3;
                ldsm4t(r0, r1, r2, r3, base + OFF_AL + boff[p][ka]);
                bl[2 * p][0] = r0; bl[2 * p][1] = r1;
                bl[2 * p + 1][0] = r2; bl[2 * p + 1][1] = r3;
            }
            #pragma unroll
            for (int ma = 0; ma < 2; ma++)
                #pragma unroll
                for (int na = 0; na < 4; na++) {
                    mma_bf16(acc[ma][na], ah[ma], bh[na]);
                    mma_bf16(acc[ma][na], ah[ma], bl[na]);
                    mma_bf16(acc[ma][na], al[ma], bh[na]);
                }
        }
        __syncthreads();
    }

    #pragma unroll
    for (int ma = 0; ma < 2; ma++) {
        int jA = j0 + wm * 32 + ma * 16 + gid;
        int jB = jA + 8;
        float bA = bias[jA], bB = bias[jB];
        #pragma unroll
        for (int na = 0; na < 4; na++) {
            int n = n0 + wn * 32 + na * 8 + tig * 2;
            float v0 = acc[ma][na][0] + bA;
            float v1 = acc[ma][na][1] + bA;
            float v2 = acc[ma][na][2] + bB;
            float v3 = acc[ma][na][3] + bB;
            if (EPI == 1) {
                v0 = gelu_f(v0); v1 = gelu_f(v1); v2 = gelu_f(v2); v3 = gelu_f(v3);
                __nv_bfloat16 h0,h1,h2,h3,l0,l1,l2,l3;
                splitbf(v0,h0,l0); splitbf(v1,h1,l1);
                splitbf(v2,h2,l2); splitbf(v3,h3,l3);
                ushort2 hA = { __bfloat16_as_ushort(h0), __bfloat16_as_ushort(h1) };
                ushort2 lA = { __bfloat16_as_ushort(l0), __bfloat16_as_ushort(l1) };
                ushort2 hB = { __bfloat16_as_ushort(h2), __bfloat16_as_ushort(h3) };
                ushort2 lB = { __bfloat16_as_ushort(l2), __bfloat16_as_ushort(l3) };
                *(ushort2*)&outh[(size_t)jA * NTOK + n] = hA;
                *(ushort2*)&outl[(size_t)jA * NTOK + n] = lA;
                *(ushort2*)&outh[(size_t)jB * NTOK + n] = hB;
                *(ushort2*)&outl[(size_t)jB * NTOK + n] = lB;
            } else {
                if (EPI == 2) {
                    float2 rA = *(const float2*)&Rres[(size_t)jA * NTOK + n];
                    float2 rB = *(const float2*)&Rres[(size_t)jB * NTOK + n];
                    v0 += rA.x; v1 += rA.y; v2 += rB.x; v3 += rB.y;
                }
                float2 oA = {v0, v1}, oB = {v2, v3};
                *(float2*)&outf[(size_t)jA * NTOK + n] = oA;
                *(float2*)&outf[(size_t)jB * NTOK + n] = oB;
            }
        }
    }
}

// ---------------- neighborhood attention (K=3, 27 taps), direct gather -------
__global__ __launch_bounds__(256)
void natten_kernel(const float* __restrict__ qkv,
                   const float* __restrict__ rpb,
                   __nv_bfloat16* __restrict__ outh,
                   __nv_bfloat16* __restrict__ outl)
{
    const int lane = threadIdx.x & 31;
    const int hh   = threadIdx.x >> 5;
    const int ih   = blockIdx.x >> 5;
    const int iw   = blockIdx.x & 31;
    const int iz   = lane;
    const int n    = (ih * 32 + iw) * 32 + iz;

    int sh = ih - 1; sh = sh < 0 ? 0 : (sh > 29 ? 29 : sh);
    int sw = iw - 1; sw = sw < 0 ? 0 : (sw > 29 ? 29 : sw);
    int sz = iz - 1; sz = sz < 0 ? 0 : (sz > 29 ? 29 : sz);

    const float scale = 0.25f;
    float q[HD];
    #pragma unroll
    for (int d = 0; d < HD; d++)
        q[d] = qkv[(size_t)(hh * HD + d) * NTOK + n] * scale;

    float lg[27];
    float mx = -1e30f;
    #pragma unroll
    for (int a = 0; a < 3; a++)
    #pragma unroll
    for (int b = 0; b < 3; b++)
    #pragma unroll
    for (int c = 0; c < 3; c++) {
        int nh = sh + a, nw = sw + b, nz = sz + c;
        int nn = (nh * 32 + nw) * 32 + nz;
        float s = 0.0f;
        #pragma unroll
        for (int d = 0; d < HD; d++)
            s = fmaf(q[d], qkv[(size_t)(CDIM + hh * HD + d) * NTOK + nn], s);
        int rh = nh - ih + 2, rw = nw - iw + 2, rz = nz - iz + 2;
        s += rpb[((hh * 5 + rh) * 5 + rw) * 5 + rz];
        lg[(a * 3 + b) * 3 + c] = s;
        mx = fmaxf(mx, s);
    }

    float denom = 0.0f;
    #pragma unroll
    for (int i = 0; i < 27; i++) { lg[i] = __expf(lg[i] - mx); denom += lg[i]; }
    const float inv = 1.0f / denom;

    float o[HD];
    #pragma unroll
    for (int d = 0; d < HD; d++) o[d] = 0.0f;
    #pragma unroll
    for (int a = 0; a < 3; a++)
    #pragma unroll
    for (int b = 0; b < 3; b++)
    #pragma unroll
    for (int c = 0; c < 3; c++) {
        int nh = sh + a, nw = sw + b, nz = sz + c;
        int nn = (nh * 32 + nw) * 32 + nz;
        float w = lg[(a * 3 + b) * 3 + c] * inv;
        #pragma unroll
        for (int d = 0; d < HD; d++)
            o[d] = fmaf(w, qkv[(size_t)(2 * CDIM + hh * HD + d) * NTOK + nn], o[d]);
    }
    #pragma unroll
    for (int d = 0; d < HD; d++) {
        __nv_bfloat16 vh, vl;
        splitbf(o[d], vh, vl);
        outh[(size_t)(hh * HD + d) * NTOK + n] = vh;
        outl[(size_t)(hh * HD + d) * NTOK + n] = vl;
    }
}

// ---------------- instance norm: 3-phase, 1024-way parallel -------------------
__global__ __launch_bounds__(256)
void in_part_kernel(const float* __restrict__ in)
{
    const int c = blockIdx.x >> 3, seg = blockIdx.x & 7;
    const float4* p = (const float4*)(in + (size_t)c * NTOK + seg * 4096);
    float s = 0.0f, s2 = 0.0f;
    #pragma unroll
    for (int i = 0; i < 4; i++) {
        float4 v = p[threadIdx.x + i * 256];
        s  += v.x + v.y + v.z + v.w;
        s2 += v.x * v.x + v.y * v.y + v.z * v.z + v.w * v.w;
    }
    #pragma unroll
    for (int o = 16; o > 0; o >>= 1) {
        s  += __shfl_down_sync(0xffffffffu, s,  o);
        s2 += __shfl_down_sync(0xffffffffu, s2, o);
    }
    __shared__ float rs[8], rq[8];
    if ((threadIdx.x & 31) == 0) { rs[threadIdx.x >> 5] = s; rq[threadIdx.x >> 5] = s2; }
    __syncthreads();
    if (threadIdx.x == 0) {
        float ts = 0.0f, tq = 0.0f;
        #pragma unroll
        for (int i = 0; i < 8; i++) { ts += rs[i]; tq += rq[i]; }
        g_sum[c * 8 + seg] = ts;
        g_sq [c * 8 + seg] = tq;
    }
}

__global__ __launch_bounds__(128)
void in_fin_kernel()
{
    const int c = threadIdx.x;
    float s = 0.0f, s2 = 0.0f;
    #pragma unroll
    for (int i = 0; i < 8; i++) { s += g_sum[c * 8 + i]; s2 += g_sq[c * 8 + i]; }
    float m = s * (1.0f / NTOK);
    float v = s2 * (1.0f / NTOK) - m * m;
    g_mean[c] = m;
    g_rstd[c] = rsqrtf(v + 1e-5f);
}

template<int SPLIT>
__global__ __launch_bounds__(256)
void in_norm_kernel(const float* __restrict__ in, float* __restrict__ out,
                    __nv_bfloat16* __restrict__ oh, __nv_bfloat16* __restrict__ ol)
{
    const int c = blockIdx.x >> 3, seg = blockIdx.x & 7;
    const float m = g_mean[c], r = g_rstd[c];
    const size_t off = (size_t)c * NTOK + seg * 4096;
    const float4* p = (const float4*)(in + off);
    float4* qo = (float4*)(out + off);
    #pragma unroll
    for (int i = 0; i < 4; i++) {
        int idx = threadIdx.x + i * 256;
        float4 v = p[idx];
        v.x = (v.x - m) * r; v.y = (v.y - m) * r;
        v.z = (v.z - m) * r; v.w = (v.w - m) * r;
        qo[idx] = v;
        if (SPLIT) {
            __nv_bfloat16 h0,h1,h2,h3,l0,l1,l2,l3;
            splitbf(v.x,h0,l0); splitbf(v.y,h1,l1); splitbf(v.z,h2,l2); splitbf(v.w,h3,l3);
            ushort4 hv = { __bfloat16_as_ushort(h0), __bfloat16_as_ushort(h1),
                           __bfloat16_as_ushort(h2), __bfloat16_as_ushort(h3) };
            ushort4 lv = { __bfloat16_as_ushort(l0), __bfloat16_as_ushort(l1),
                           __bfloat16_as_ushort(l2), __bfloat16_as_ushort(l3) };
            ((ushort4*)(oh + off))[idx] = hv;
            ((ushort4*)(ol + off))[idx] = lv;
        }
    }
}

// ---------------- launch ------------------------------------------------------
extern "C" void kernel_launch(void* const* d_in, const int* in_sizes, int n_in,
                              void* d_out, int out_size)
{
    (void)in_sizes; (void)n_in; (void)out_size;
    const float* x      = (const float*)d_in[0];
    const float* w_qkv  = (const float*)d_in[1];
    const float* b_qkv  = (const float*)d_in[2];
    const float* rpb    = (const float*)d_in[3];
    const float* w_proj = (const float*)d_in[4];
    const float* b_proj = (const float*)d_in[5];
    const float* w_ffn1 = (const float*)d_in[6];
    const float* b_ffn1 = (const float*)d_in[7];
    const float* w_ffn2 = (const float*)d_in[8];
    const float* b_ffn2 = (const float*)d_in[9];
    float* out = (float*)d_out;

    float *qkv, *x5, *t, *y;
    __nv_bfloat16 *xh,*xl,*ah,*al,*th,*tl,*hh,*hl;
    __nv_bfloat16 *wqh,*wql,*wph,*wpl,*w1h,*w1l,*w2h,*w2l;
    cudaGetSymbolAddress((void**)&qkv, g_qkv);
    cudaGetSymbolAddress((void**)&x5,  g_x5);
    cudaGetSymbolAddress((void**)&t,   g_t);
    cudaGetSymbolAddress((void**)&y,   g_y);
    cudaGetSymbolAddress((void**)&xh,  g_xh);  cudaGetSymbolAddress((void**)&xl, g_xl);
    cudaGetSymbolAddress((void**)&ah,  g_ah);  cudaGetSymbolAddress((void**)&al, g_al);
    cudaGetSymbolAddress((void**)&th,  g_th);  cudaGetSymbolAddress((void**)&tl, g_tl);
    cudaGetSymbolAddress((void**)&hh,  g_hh);  cudaGetSymbolAddress((void**)&hl, g_hl);
    cudaGetSymbolAddress((void**)&wqh, g_wqh); cudaGetSymbolAddress((void**)&wql, g_wql);
    cudaGetSymbolAddress((void**)&wph, g_wph); cudaGetSymbolAddress((void**)&wpl, g_wpl);
    cudaGetSymbolAddress((void**)&w1h, g_w1h); cudaGetSymbolAddress((void**)&w1l, g_w1l);
    cudaGetSymbolAddress((void**)&w2h, g_w2h); cudaGetSymbolAddress((void**)&w2l, g_w2l);

    cudaFuncSetAttribute(gemm_tc<0>, cudaFuncAttributeMaxDynamicSharedMemorySize, SMEM_TOT);
    cudaFuncSetAttribute(gemm_tc<1>, cudaFuncAttributeMaxDynamicSharedMemorySize, SMEM_TOT);
    cudaFuncSetAttribute(gemm_tc<2>, cudaFuncAttributeMaxDynamicSharedMemorySize, SMEM_TOT);

    // 0) splits: x + all weights (one launch)
    split_kernel<<<4096, 256>>>(x, xh, xl, CDIM * NTOK / 4);
    wsplit_kernel<<<192, 256>>>(w_qkv, wqh, wql, w_proj, wph, wpl,
                                w_ffn1, w1h, w1l, w_ffn2, w2h, w2l);

    // 1) QKV -> fp32 [384][N]
    gemm_tc<0><<<dim3(NTOK / 128, 384 / 64), 256, SMEM_TOT>>>(
        xh, xl, wqh, wql, b_qkv, nullptr, qkv, nullptr, nullptr, CDIM);
    // 2) natten -> attn split bf16
    natten_kernel<<<1024, 256>>>(qkv, rpb, ah, al);
    // 3) proj -> x5 fp32
    gemm_tc<0><<<dim3(NTOK / 128, 128 / 64), 256, SMEM_TOT>>>(
        ah, al, wph, wpl, b_proj, nullptr, x5, nullptr, nullptr, CDIM);
    // 4) inorm1 -> t fp32 + split
    in_part_kernel<<<1024, 256>>>(x5);
    in_fin_kernel<<<1, 128>>>();
    in_norm_kernel<1><<<1024, 256>>>(x5, t, th, tl);
    // 5) FFN1 + gelu -> hidden split bf16
    gemm_tc<1><<<dim3(NTOK / 128, 512 / 64), 256, SMEM_TOT>>>(
        th, tl, w1h, w1l, b_ffn1, nullptr, nullptr, hh, hl, CDIM);
    // 6) FFN2 + residual(t) -> y fp32
    gemm_tc<2><<<dim3(NTOK / 128, 128 / 64), 256, SMEM_TOT>>>(
        hh, hl, w2h, w2l, b_ffn2, t, y, nullptr, nullptr, CF);
    // 7) final inorm -> out
    in_part_kernel<<<1024, 256>>>(y);
    in_fin_kernel<<<1, 128>>>();
    in_norm_kernel<0><<<1024, 256>>>(y, out, nullptr, nullptr);
}